// round 3
// baseline (speedup 1.0000x reference)
#include <cuda_runtime.h>

#define ALPHA 0.2f
#define B_   8
#define G_   8
#define V_   1024
#define FIN_ 64
#define FOUT_ 64
#define C_   512            // G_*FOUT_
#define OUTW_ 60            // FOUT_-4
#define OUTC_ 120           // 2*OUTW_

typedef unsigned long long ull;

// ---------------- scratch (device globals; no allocation) ----------------
__device__ __align__(16) float    g_Wh[B_*V_*C_];        // [b][v][c] leaky(Wh)
__device__ float                  g_Spart[B_*16*C_];     // partial col sums per v-tile
__device__ float                  g_S[B_*C_];            // col sums of leaky(Wh)
__device__ unsigned               g_rowmask[B_*V_*32];   // bit j set <=> a[b,i,j]==0
__device__ int                    g_zcol[B_*V_];         // zero count per column v
// interleaved (fin, fout) pairs: [b][g][v][o] of float2
__device__ __align__(16) float2   g_feat2[B_*G_*V_*FOUT_];

__device__ __forceinline__ float lrelu(float x) { return x >= 0.f ? x : ALPHA * x; }

// ---- packed fp32x2 helpers (SASS FFMA2; PTX-only pattern) ----
__device__ __forceinline__ ull fma2(ull a, ull b, ull c) {
    ull d;
    asm("fma.rn.f32x2 %0, %1, %2, %3;" : "=l"(d) : "l"(a), "l"(b), "l"(c));
    return d;
}
__device__ __forceinline__ float2 unpack2(ull v) {
    float2 r;
    asm("mov.b64 {%0, %1}, %2;" : "=f"(r.x), "=f"(r.y) : "l"(v));
    return r;
}

// ---------------- K0: zero the column-zero counters ----------------
__global__ void k_zero() {
    int t = blockIdx.x * blockDim.x + threadIdx.x;
    if (t < B_ * V_) g_zcol[t] = 0;
}

// ---------------- K2: adj scan -> zero-edge bitmask + column zero counts ------
__global__ void __launch_bounds__(256) k_adj(const int* __restrict__ adj) {
    int i = blockIdx.x, b = blockIdx.y;
    __shared__ unsigned mask[32];
    int t = threadIdx.x;
    if (t < 32) mask[t] = 0u;
    __syncthreads();

    const int4* p = (const int4*)(adj + (size_t)b * G_ * V_ * V_ + (size_t)i * V_);
    int4 acc = p[t];
#pragma unroll
    for (int g = 1; g < G_; g++) {
        int4 v = p[(size_t)g * (V_ * (V_ / 4)) + t];
        acc.x |= v.x; acc.y |= v.y; acc.z |= v.z; acc.w |= v.w;
    }
    unsigned nib = (unsigned)(acc.x == 0) | ((unsigned)(acc.y == 0) << 1) |
                   ((unsigned)(acc.z == 0) << 2) | ((unsigned)(acc.w == 0) << 3);
    if (nib) {
        atomicOr(&mask[t >> 3], nib << ((t & 7) * 4));
        int jb = b * V_ + 4 * t;
        if (acc.x == 0) atomicAdd(&g_zcol[jb + 0], 1);
        if (acc.y == 0) atomicAdd(&g_zcol[jb + 1], 1);
        if (acc.z == 0) atomicAdd(&g_zcol[jb + 2], 1);
        if (acc.w == 0) atomicAdd(&g_zcol[jb + 3], 1);
    }
    __syncthreads();
    if (t < 32) g_rowmask[((size_t)b * V_ + i) * 32 + t] = mask[t];
}

// ---------------- K1: Wh = leaky(h @ W) per (b,g); also partial column sums ----
__global__ void __launch_bounds__(256) k_wh(const float* __restrict__ h,
                                            const float* __restrict__ W) {
    __shared__ __align__(16) float sW[64 * 64];   // [i][o]
    __shared__ __align__(16) float sH[64 * 64];   // [v][i]
    __shared__ float red[64 * 17];

    int t = threadIdx.x;
    int vt = blockIdx.x, g = blockIdx.y, b = blockIdx.z;

    const float4* wp = (const float4*)(W + (size_t)g * 4096);
    const float4* hp = (const float4*)(h + (((size_t)b * G_ + g) * V_ + (size_t)vt * 64) * 64);
    float4* sw4 = (float4*)sW;
    float4* sh4 = (float4*)sH;
#pragma unroll
    for (int q = t; q < 1024; q += 256) { sw4[q] = wp[q]; sh4[q] = hp[q]; }
    __syncthreads();

    int tx = t & 15, ty = t >> 4;
    int o0 = tx * 4, r0 = ty * 4;
    float acc[4][4] = {};
#pragma unroll 4
    for (int i = 0; i < 64; i++) {
        float4 bb = *(const float4*)(sW + i * 64 + o0);
#pragma unroll
        for (int r = 0; r < 4; r++) {
            float a = sH[(r0 + r) * 64 + i];
            acc[r][0] += a * bb.x; acc[r][1] += a * bb.y;
            acc[r][2] += a * bb.z; acc[r][3] += a * bb.w;
        }
    }

    float cs[4] = {0.f, 0.f, 0.f, 0.f};
#pragma unroll
    for (int r = 0; r < 4; r++) {
        float4 v;
        v.x = lrelu(acc[r][0]); v.y = lrelu(acc[r][1]);
        v.z = lrelu(acc[r][2]); v.w = lrelu(acc[r][3]);
        size_t row = (size_t)b * V_ + vt * 64 + r0 + r;
        *(float4*)(g_Wh + row * C_ + g * 64 + o0) = v;
        cs[0] += v.x; cs[1] += v.y; cs[2] += v.z; cs[3] += v.w;
    }
    __syncthreads();
#pragma unroll
    for (int j = 0; j < 4; j++) red[(o0 + j) * 17 + ty] = cs[j];
    __syncthreads();
    if (t < 64) {
        float s = 0.f;
#pragma unroll
        for (int k = 0; k < 16; k++) s += red[t * 17 + k];
        g_Spart[((size_t)b * 16 + vt) * C_ + g * 64 + t] = s;
    }
}

// ---------------- K1b: reduce partial sums -> S ----------------
__global__ void k_sreduce() {
    int b = blockIdx.x, c = threadIdx.x;   // 8 blocks x 512
    float s = 0.f;
#pragma unroll
    for (int vt = 0; vt < 16; vt++) s += g_Spart[((size_t)b * 16 + vt) * C_ + c];
    g_S[b * C_ + c] = s;
}

// ---------------- K3: assemble (fin, fout) interleaved ----------------
// fout[b,i,c] = leaky((S[b,c] - sum_{j in zeros(b,i)} Wh[b,j,c]) / V)
// fin [b,i,c] = leaky(deg[b,i] * Wh[b,i,c])
// Warp 0 builds an explicit zero-j list; corr loads issued 4 at a time.
__global__ void __launch_bounds__(512) k_feat() {
    int i = blockIdx.x, b = blockIdx.y;
    int c = threadIdx.x;
    __shared__ short jlist[64];
    __shared__ int njs;
    __shared__ float sdeg;

    if (c == 0) sdeg = (float)(V_ - g_zcol[b * V_ + i]) * (1.0f / V_);
    if (c < 32) {
        unsigned mw = g_rowmask[((size_t)b * V_ + i) * 32 + c];
        int cnt = __popc(mw);
        int pre = cnt;
#pragma unroll
        for (int d = 1; d < 32; d <<= 1) {
            int v = __shfl_up_sync(0xffffffffu, pre, d);
            if (c >= d) pre += v;
        }
        int excl = pre - cnt;
        if (c == 31) njs = pre;
        while (mw) {
            int p = __ffs(mw) - 1;
            mw &= mw - 1;
            jlist[excl++] = (short)(c * 32 + p);
        }
    }
    __syncthreads();

    float S = g_S[b * C_ + c];
    float corr = 0.f;
    int n = njs;
    const float* whb = g_Wh + (size_t)b * V_ * C_ + c;
#pragma unroll 1
    for (int k = 0; k < n; k += 4) {
        int j0 = jlist[k];
        float v0 = whb[(size_t)j0 * C_];
        float v1 = (k + 1 < n) ? whb[(size_t)jlist[k + 1] * C_] : 0.f;
        float v2 = (k + 2 < n) ? whb[(size_t)jlist[k + 2] * C_] : 0.f;
        float v3 = (k + 3 < n) ? whb[(size_t)jlist[k + 3] * C_] : 0.f;
        corr += (v0 + v1) + (v2 + v3);
    }
    float fout = lrelu((S - corr) * (1.0f / V_));
    float fin  = lrelu(sdeg * whb[(size_t)i * C_]);

    int g = c >> 6, o = c & 63;
    g_feat2[(((size_t)b * G_ + g) * V_ + i) * FOUT_ + o] = make_float2(fin, fout);
}

// ---------------- K4: both 5x5 convs at once, f32x2 lanes = (conv1, conv2) ----
// grid (V/16, B), block 960: cg(15) x rg(8) x g(8). Thread: 1 channel, 2 rows,
// 4 cols, both convs packed in lanes. Zero broadcast MOVs: inputs are native
// float2 pairs in smem, weights pre-paired (w1,w2) as ull.
__global__ void __launch_bounds__(960, 1) k_conv(const float* __restrict__ cw1,
                                                 const float* __restrict__ cb1,
                                                 const float* __restrict__ cw2,
                                                 const float* __restrict__ cb2,
                                                 float* __restrict__ out) {
    extern __shared__ char sm_[];
    float2* tile = (float2*)sm_;                    // [8][20][64]
    float2* wts  = (float2*)(sm_ + 81920);          // [g][cin][25] -> (w1,w2)
    float2* sb   = (float2*)(sm_ + 81920 + 12800);  // [8]

    int b = blockIdx.y;
    int r0 = blockIdx.x * 16;
    int t = threadIdx.x;

    for (int q = t; q < 1600; q += 960)
        wts[q] = make_float2(cw1[q], cw2[q]);
    if (t < 8) sb[t] = make_float2(cb1[t], cb2[t]);

    // stage: 8 cin x 20 rows x 64 float2 = 5120 float4
#pragma unroll 1
    for (int q = t; q < 5120; q += 960) {
        int cin = q / 640;
        int rem = q - cin * 640;
        int row = rem >> 5;
        int p4  = rem & 31;
        int v = r0 - 2 + row;
        float4 val = make_float4(0.f, 0.f, 0.f, 0.f);
        if (v >= 0 && v < V_)
            val = *(const float4*)(g_feat2 + (((size_t)b * G_ + cin) * V_ + v) * FOUT_ + p4 * 2);
        *(float4*)(tile + (cin * 20 + row) * 64 + p4 * 2) = val;
    }
    __syncthreads();

    int cg = t % 15;
    int rem = t / 15;
    int rg = rem & 7;
    int g  = rem >> 3;
    int w0 = cg * 4;
    int lr = rg * 2;

    ull bias = *(const ull*)&sb[g];
    ull acc[2][4];
#pragma unroll
    for (int r = 0; r < 2; r++)
#pragma unroll
        for (int cc = 0; cc < 4; cc++) acc[r][cc] = bias;

#pragma unroll 1
    for (int cin = 0; cin < 8; cin++) {
        const ull* wp = (const ull*)(wts + (g * 8 + cin) * 25);
        const float2* tb = tile + (cin * 20 + lr) * 64 + w0;
#pragma unroll
        for (int ri = 0; ri < 6; ri++) {
            ulonglong2 u01 = *(const ulonglong2*)(tb + ri * 64);
            ulonglong2 u23 = *(const ulonglong2*)(tb + ri * 64 + 2);
            ulonglong2 u45 = *(const ulonglong2*)(tb + ri * 64 + 4);
            ulonglong2 u67 = *(const ulonglong2*)(tb + ri * 64 + 6);
            ull x[8] = {u01.x, u01.y, u23.x, u23.y, u45.x, u45.y, u67.x, u67.y};
            if (ri <= 4) {          // contributes to acc row 0 at kh = ri
#pragma unroll
                for (int kw = 0; kw < 5; kw++) {
                    ull wt = wp[ri * 5 + kw];
#pragma unroll
                    for (int cc = 0; cc < 4; cc++)
                        acc[0][cc] = fma2(x[kw + cc], wt, acc[0][cc]);
                }
            }
            if (ri >= 1) {          // contributes to acc row 1 at kh = ri-1
#pragma unroll
                for (int kw = 0; kw < 5; kw++) {
                    ull wt = wp[(ri - 1) * 5 + kw];
#pragma unroll
                    for (int cc = 0; cc < 4; cc++)
                        acc[1][cc] = fma2(x[kw + cc], wt, acc[1][cc]);
                }
            }
        }
    }

#pragma unroll
    for (int r = 0; r < 2; r++) {
        float2 u0 = unpack2(acc[r][0]);
        float2 u1 = unpack2(acc[r][1]);
        float2 u2 = unpack2(acc[r][2]);
        float2 u3 = unpack2(acc[r][3]);
        int v = r0 + lr + r;
        size_t base = (((size_t)b * G_ + g) * V_ + v) * OUTC_;
        *(float4*)(out + base + w0)         = make_float4(u0.x, u1.x, u2.x, u3.x);
        *(float4*)(out + base + OUTW_ + w0) = make_float4(u0.y, u1.y, u2.y, u3.y);
    }
}

#define CONV_SMEM (81920 + 12800 + 64)

// ---------------- launch ----------------
extern "C" void kernel_launch(void* const* d_in, const int* in_sizes, int n_in,
                              void* d_out, int out_size) {
    const float* h       = (const float*)d_in[0];
    const int*   adj     = (const int*)d_in[1];
    const float* W       = (const float*)d_in[2];
    const float* conv1_w = (const float*)d_in[3];
    const float* conv1_b = (const float*)d_in[4];
    const float* conv2_w = (const float*)d_in[5];
    const float* conv2_b = (const float*)d_in[6];
    float* out = (float*)d_out;

    cudaFuncSetAttribute(k_conv, cudaFuncAttributeMaxDynamicSharedMemorySize, CONV_SMEM);

    // adj FIRST: its 268MB stream would evict g_Wh from L2 if run after k_wh.
    k_zero<<<8, 1024>>>();
    k_adj<<<dim3(V_, B_), 256>>>(adj);
    k_wh<<<dim3(16, G_, B_), 256>>>(h, W);
    k_sreduce<<<B_, 512>>>();
    k_feat<<<dim3(V_, B_), 512>>>();
    k_conv<<<dim3(V_ / 16, B_), 960, CONV_SMEM>>>(conv1_w, conv1_b, conv2_w, conv2_b, out);
}

// round 4
// speedup vs baseline: 1.0315x; 1.0315x over previous
#include <cuda_runtime.h>

#define ALPHA 0.2f
#define B_   8
#define G_   8
#define V_   1024
#define FIN_ 64
#define FOUT_ 64
#define C_   512            // G_*FOUT_
#define OUTW_ 60            // FOUT_-4
#define OUTC_ 120           // 2*OUTW_

typedef unsigned long long ull;

// ---------------- scratch (device globals; no allocation) ----------------
__device__ __align__(16) float    g_Wh[B_*V_*C_];        // [b][v][c] leaky(Wh)
__device__ float                  g_Spart[B_*16*C_];     // partial col sums per v-tile
__device__ float                  g_S[B_*C_];            // col sums of leaky(Wh)
__device__ unsigned               g_rowmask[B_*V_*32];   // bit j set <=> a[b,i,j]==0
__device__ int                    g_zcol[B_*V_];         // zero count per column v
__device__ __align__(16) float    g_featin[B_*G_*V_*FOUT_];
__device__ __align__(16) float    g_featout[B_*G_*V_*FOUT_];

__device__ __forceinline__ float lrelu(float x) { return x >= 0.f ? x : ALPHA * x; }

// ---- packed fp32x2 helpers (SASS FFMA2; PTX-only pattern) ----
__device__ __forceinline__ ull pack2(float x, float y) {
    ull r;
    asm("mov.b64 %0, {%1, %2};" : "=l"(r) : "f"(x), "f"(y));
    return r;
}
__device__ __forceinline__ ull fma2(ull a, ull b, ull c) {
    ull d;
    asm("fma.rn.f32x2 %0, %1, %2, %3;" : "=l"(d) : "l"(a), "l"(b), "l"(c));
    return d;
}
__device__ __forceinline__ float2 unpack2(ull v) {
    float2 r;
    asm("mov.b64 {%0, %1}, %2;" : "=f"(r.x), "=f"(r.y) : "l"(v));
    return r;
}

// ---------------- K0: zero the column-zero counters ----------------
__global__ void k_zero() {
    int t = blockIdx.x * blockDim.x + threadIdx.x;
    if (t < B_ * V_) g_zcol[t] = 0;
}

// ---------------- K2: adj scan -> zero-edge bitmask + column zero counts ------
__global__ void __launch_bounds__(256) k_adj(const int* __restrict__ adj) {
    int i = blockIdx.x, b = blockIdx.y;
    __shared__ unsigned mask[32];
    int t = threadIdx.x;
    if (t < 32) mask[t] = 0u;
    __syncthreads();

    const int4* p = (const int4*)(adj + (size_t)b * G_ * V_ * V_ + (size_t)i * V_);
    int4 acc = p[t];
#pragma unroll
    for (int g = 1; g < G_; g++) {
        int4 v = p[(size_t)g * (V_ * (V_ / 4)) + t];
        acc.x |= v.x; acc.y |= v.y; acc.z |= v.z; acc.w |= v.w;
    }
    unsigned nib = (unsigned)(acc.x == 0) | ((unsigned)(acc.y == 0) << 1) |
                   ((unsigned)(acc.z == 0) << 2) | ((unsigned)(acc.w == 0) << 3);
    if (nib) {
        atomicOr(&mask[t >> 3], nib << ((t & 7) * 4));
        int jb = b * V_ + 4 * t;
        if (acc.x == 0) atomicAdd(&g_zcol[jb + 0], 1);
        if (acc.y == 0) atomicAdd(&g_zcol[jb + 1], 1);
        if (acc.z == 0) atomicAdd(&g_zcol[jb + 2], 1);
        if (acc.w == 0) atomicAdd(&g_zcol[jb + 3], 1);
    }
    __syncthreads();
    if (t < 32) g_rowmask[((size_t)b * V_ + i) * 32 + t] = mask[t];
}

// ---------------- K1: Wh = leaky(h @ W) per (b,g); also partial column sums ----
__global__ void __launch_bounds__(256) k_wh(const float* __restrict__ h,
                                            const float* __restrict__ W) {
    __shared__ __align__(16) float sW[64 * 64];   // [i][o]
    __shared__ __align__(16) float sH[64 * 64];   // [v][i]
    __shared__ float red[64 * 17];

    int t = threadIdx.x;
    int vt = blockIdx.x, g = blockIdx.y, b = blockIdx.z;

    const float4* wp = (const float4*)(W + (size_t)g * 4096);
    const float4* hp = (const float4*)(h + (((size_t)b * G_ + g) * V_ + (size_t)vt * 64) * 64);
    float4* sw4 = (float4*)sW;
    float4* sh4 = (float4*)sH;
#pragma unroll
    for (int q = t; q < 1024; q += 256) { sw4[q] = wp[q]; sh4[q] = hp[q]; }
    __syncthreads();

    int tx = t & 15, ty = t >> 4;
    int o0 = tx * 4, r0 = ty * 4;
    float acc[4][4] = {};
#pragma unroll 4
    for (int i = 0; i < 64; i++) {
        float4 bb = *(const float4*)(sW + i * 64 + o0);
#pragma unroll
        for (int r = 0; r < 4; r++) {
            float a = sH[(r0 + r) * 64 + i];
            acc[r][0] += a * bb.x; acc[r][1] += a * bb.y;
            acc[r][2] += a * bb.z; acc[r][3] += a * bb.w;
        }
    }

    float cs[4] = {0.f, 0.f, 0.f, 0.f};
#pragma unroll
    for (int r = 0; r < 4; r++) {
        float4 v;
        v.x = lrelu(acc[r][0]); v.y = lrelu(acc[r][1]);
        v.z = lrelu(acc[r][2]); v.w = lrelu(acc[r][3]);
        size_t row = (size_t)b * V_ + vt * 64 + r0 + r;
        *(float4*)(g_Wh + row * C_ + g * 64 + o0) = v;
        cs[0] += v.x; cs[1] += v.y; cs[2] += v.z; cs[3] += v.w;
    }
    __syncthreads();
#pragma unroll
    for (int j = 0; j < 4; j++) red[(o0 + j) * 17 + ty] = cs[j];
    __syncthreads();
    if (t < 64) {
        float s = 0.f;
#pragma unroll
        for (int k = 0; k < 16; k++) s += red[t * 17 + k];
        g_Spart[((size_t)b * 16 + vt) * C_ + g * 64 + t] = s;
    }
}

// ---------------- K1b: reduce partial sums -> S ----------------
__global__ void k_sreduce() {
    int b = blockIdx.x, c = threadIdx.x;   // 8 blocks x 512
    float s = 0.f;
#pragma unroll
    for (int vt = 0; vt < 16; vt++) s += g_Spart[((size_t)b * 16 + vt) * C_ + c];
    g_S[b * C_ + c] = s;
}

// ---------------- K3: assemble feature_in / feature_out planes ----------------
__global__ void __launch_bounds__(512) k_feat() {
    int i = blockIdx.x, b = blockIdx.y;
    int c = threadIdx.x;
    __shared__ short jlist[64];
    __shared__ int njs;
    __shared__ float sdeg;

    if (c == 0) sdeg = (float)(V_ - g_zcol[b * V_ + i]) * (1.0f / V_);
    if (c < 32) {
        unsigned mw = g_rowmask[((size_t)b * V_ + i) * 32 + c];
        int cnt = __popc(mw);
        int pre = cnt;
#pragma unroll
        for (int d = 1; d < 32; d <<= 1) {
            int v = __shfl_up_sync(0xffffffffu, pre, d);
            if (c >= d) pre += v;
        }
        int excl = pre - cnt;
        if (c == 31) njs = pre;
        while (mw) {
            int p = __ffs(mw) - 1;
            mw &= mw - 1;
            jlist[excl++] = (short)(c * 32 + p);
        }
    }
    __syncthreads();

    float S = g_S[b * C_ + c];
    float corr = 0.f;
    int n = njs;
    const float* whb = g_Wh + (size_t)b * V_ * C_ + c;
#pragma unroll 1
    for (int k = 0; k < n; k += 4) {
        float v0 = whb[(size_t)jlist[k] * C_];
        float v1 = (k + 1 < n) ? whb[(size_t)jlist[k + 1] * C_] : 0.f;
        float v2 = (k + 2 < n) ? whb[(size_t)jlist[k + 2] * C_] : 0.f;
        float v3 = (k + 3 < n) ? whb[(size_t)jlist[k + 3] * C_] : 0.f;
        corr += (v0 + v1) + (v2 + v3);
    }
    float fout = lrelu((S - corr) * (1.0f / V_));
    float fin  = lrelu(sdeg * whb[(size_t)i * C_]);

    int g = c >> 6, o = c & 63;
    size_t oidx = (((size_t)b * G_ + g) * V_ + i) * FOUT_ + o;
    g_featin[oidx]  = fin;
    g_featout[oidx] = fout;
}

// ---------------- K4: both 5x5 convs fused, f32x2 lanes = (conv1, conv2) ------
// grid (V/16, B), 480 threads: cg(15) x rg(4) x g(8). Thread: 4 rows x 4 cols,
// 1 channel, both convs packed. Tile stored as TWO float planes (16B lane
// stride -> conflict-free LDS.128); lanes packed via mov.b64 just before FMA.
#define T1_OFF 0
#define T2_OFF 40960
#define WT_OFF 81920
#define SB_OFF 94720
#define CONV_SMEM (94720 + 64)

__global__ void __launch_bounds__(480, 1) k_conv(const float* __restrict__ cw1,
                                                 const float* __restrict__ cb1,
                                                 const float* __restrict__ cw2,
                                                 const float* __restrict__ cb2,
                                                 float* __restrict__ out) {
    extern __shared__ char sm_[];
    float*  t1  = (float*)(sm_ + T1_OFF);        // [8][20][64]
    float*  t2  = (float*)(sm_ + T2_OFF);        // [8][20][64]
    float2* wts = (float2*)(sm_ + WT_OFF);       // [g][cin][25] -> (w1,w2)
    float2* sb  = (float2*)(sm_ + SB_OFF);       // [8]

    int b = blockIdx.y;
    int r0 = blockIdx.x * 16;
    int t = threadIdx.x;

    for (int q = t; q < 1600; q += 480)
        wts[q] = make_float2(cw1[q], cw2[q]);
    if (t < 8) sb[t] = make_float2(cb1[t], cb2[t]);

    // stage both planes: 8 cin x 20 rows x 16 float4 = 2560 float4 per plane
#pragma unroll 1
    for (int q = t; q < 2560; q += 480) {
        int cin = q / 320;
        int rem = q - cin * 320;
        int row = rem >> 4;
        int o4  = rem & 15;
        int v = r0 - 2 + row;
        float4 v1 = make_float4(0.f, 0.f, 0.f, 0.f);
        float4 v2 = v1;
        if (v >= 0 && v < V_) {
            size_t src = (((size_t)b * G_ + cin) * V_ + v) * FOUT_ + o4 * 4;
            v1 = *(const float4*)(g_featin + src);
            v2 = *(const float4*)(g_featout + src);
        }
        int dst = (cin * 20 + row) * 64 + o4 * 4;
        *(float4*)(t1 + dst) = v1;
        *(float4*)(t2 + dst) = v2;
    }
    __syncthreads();

    int cg = t % 15;
    int rem = t / 15;
    int rg = rem & 3;
    int g  = rem >> 2;
    int w0 = cg * 4;
    int lr = rg * 4;

    ull bias = pack2(sb[g].x, sb[g].y);
    ull acc[4][4];
#pragma unroll
    for (int r = 0; r < 4; r++)
#pragma unroll
        for (int cc = 0; cc < 4; cc++) acc[r][cc] = bias;

#pragma unroll 1
    for (int cin = 0; cin < 8; cin++) {
        const ull* wp = (const ull*)(wts + (g * 8 + cin) * 25);
        const float* p1 = t1 + (cin * 20 + lr) * 64 + w0;
        const float* p2 = t2 + (cin * 20 + lr) * 64 + w0;
#pragma unroll
        for (int ri = 0; ri < 8; ri++) {
            float4 a1 = *(const float4*)(p1 + ri * 64);
            float4 b1 = *(const float4*)(p1 + ri * 64 + 4);
            float4 a2 = *(const float4*)(p2 + ri * 64);
            float4 b2 = *(const float4*)(p2 + ri * 64 + 4);
            ull x[8];
            x[0] = pack2(a1.x, a2.x); x[1] = pack2(a1.y, a2.y);
            x[2] = pack2(a1.z, a2.z); x[3] = pack2(a1.w, a2.w);
            x[4] = pack2(b1.x, b2.x); x[5] = pack2(b1.y, b2.y);
            x[6] = pack2(b1.z, b2.z); x[7] = pack2(b1.w, b2.w);
#pragma unroll
            for (int r = 0; r < 4; r++) {
                int kh = ri - r;
                if (kh < 0 || kh > 4) continue;
#pragma unroll
                for (int kw = 0; kw < 5; kw++) {
                    ull wt = wp[kh * 5 + kw];
#pragma unroll
                    for (int cc = 0; cc < 4; cc++)
                        acc[r][cc] = fma2(x[kw + cc], wt, acc[r][cc]);
                }
            }
        }
    }

#pragma unroll
    for (int r = 0; r < 4; r++) {
        float2 u0 = unpack2(acc[r][0]);
        float2 u1 = unpack2(acc[r][1]);
        float2 u2 = unpack2(acc[r][2]);
        float2 u3 = unpack2(acc[r][3]);
        int v = r0 + lr + r;
        size_t base = (((size_t)b * G_ + g) * V_ + v) * OUTC_;
        *(float4*)(out + base + w0)         = make_float4(u0.x, u1.x, u2.x, u3.x);
        *(float4*)(out + base + OUTW_ + w0) = make_float4(u0.y, u1.y, u2.y, u3.y);
    }
}

// ---------------- launch ----------------
extern "C" void kernel_launch(void* const* d_in, const int* in_sizes, int n_in,
                              void* d_out, int out_size) {
    const float* h       = (const float*)d_in[0];
    const int*   adj     = (const int*)d_in[1];
    const float* W       = (const float*)d_in[2];
    const float* conv1_w = (const float*)d_in[3];
    const float* conv1_b = (const float*)d_in[4];
    const float* conv2_w = (const float*)d_in[5];
    const float* conv2_b = (const float*)d_in[6];
    float* out = (float*)d_out;

    cudaFuncSetAttribute(k_conv, cudaFuncAttributeMaxDynamicSharedMemorySize, CONV_SMEM);

    // adj FIRST: its 268MB stream would evict g_Wh from L2 if run after k_wh.
    k_zero<<<8, 1024>>>();
    k_adj<<<dim3(V_, B_), 256>>>(adj);
    k_wh<<<dim3(16, G_, B_), 256>>>(h, W);
    k_sreduce<<<B_, 512>>>();
    k_feat<<<dim3(V_, B_), 512>>>();
    k_conv<<<dim3(V_ / 16, B_), 480, CONV_SMEM>>>(conv1_w, conv1_b, conv2_w, conv2_b, out);
}

// round 5
// speedup vs baseline: 1.1861x; 1.1499x over previous
#include <cuda_runtime.h>

#define ALPHA 0.2f
#define B_   8
#define G_   8
#define V_   1024
#define FIN_ 64
#define FOUT_ 64
#define C_   512            // G_*FOUT_
#define OUTW_ 60            // FOUT_-4
#define OUTC_ 120           // 2*OUTW_

typedef unsigned long long ull;

// ---------------- scratch (device globals; no allocation) ----------------
__device__ __align__(16) float    g_Wh[B_*V_*C_];        // [b][v][c] leaky(Wh)
__device__ float                  g_Spart[B_*16*C_];     // partial col sums per v-tile
__device__ float                  g_S[B_*C_];            // col sums of leaky(Wh)
__device__ unsigned               g_rowmask[B_*V_*32];   // bit j set <=> a[b,i,j]==0
__device__ int                    g_zcol[B_*V_];         // zero count per column v
__device__ __align__(16) float    g_featin[B_*G_*V_*FOUT_];
__device__ __align__(16) float    g_featout[B_*G_*V_*FOUT_];

__device__ __forceinline__ float lrelu(float x) { return x >= 0.f ? x : ALPHA * x; }

// ---- packed fp32x2 helpers (SASS FFMA2; PTX-only pattern) ----
__device__ __forceinline__ ull pack2(float x, float y) {
    ull r;
    asm("mov.b64 %0, {%1, %2};" : "=l"(r) : "f"(x), "f"(y));
    return r;
}
__device__ __forceinline__ ull fma2(ull a, ull b, ull c) {
    ull d;
    asm("fma.rn.f32x2 %0, %1, %2, %3;" : "=l"(d) : "l"(a), "l"(b), "l"(c));
    return d;
}
__device__ __forceinline__ float2 unpack2(ull v) {
    float2 r;
    asm("mov.b64 {%0, %1}, %2;" : "=f"(r.x), "=f"(r.y) : "l"(v));
    return r;
}

// ---------------- K0: zero the column-zero counters ----------------
__global__ void k_zero() {
    int t = blockIdx.x * blockDim.x + threadIdx.x;
    if (t < B_ * V_) g_zcol[t] = 0;
}

// ---------------- K2: adj scan -> zero-edge bitmask + column zero counts ------
__global__ void __launch_bounds__(256) k_adj(const int* __restrict__ adj) {
    int i = blockIdx.x, b = blockIdx.y;
    __shared__ unsigned mask[32];
    int t = threadIdx.x;
    if (t < 32) mask[t] = 0u;
    __syncthreads();

    const int4* p = (const int4*)(adj + (size_t)b * G_ * V_ * V_ + (size_t)i * V_);
    int4 acc = p[t];
#pragma unroll
    for (int g = 1; g < G_; g++) {
        int4 v = p[(size_t)g * (V_ * (V_ / 4)) + t];
        acc.x |= v.x; acc.y |= v.y; acc.z |= v.z; acc.w |= v.w;
    }
    unsigned nib = (unsigned)(acc.x == 0) | ((unsigned)(acc.y == 0) << 1) |
                   ((unsigned)(acc.z == 0) << 2) | ((unsigned)(acc.w == 0) << 3);
    if (nib) {
        atomicOr(&mask[t >> 3], nib << ((t & 7) * 4));
        int jb = b * V_ + 4 * t;
        if (acc.x == 0) atomicAdd(&g_zcol[jb + 0], 1);
        if (acc.y == 0) atomicAdd(&g_zcol[jb + 1], 1);
        if (acc.z == 0) atomicAdd(&g_zcol[jb + 2], 1);
        if (acc.w == 0) atomicAdd(&g_zcol[jb + 3], 1);
    }
    __syncthreads();
    if (t < 32) g_rowmask[((size_t)b * V_ + i) * 32 + t] = mask[t];
}

// ---------------- K1: Wh = leaky(h @ W) per (b,g); also partial column sums ----
__global__ void __launch_bounds__(256) k_wh(const float* __restrict__ h,
                                            const float* __restrict__ W) {
    __shared__ __align__(16) float sW[64 * 64];   // [i][o]
    __shared__ __align__(16) float sH[64 * 64];   // [v][i]
    __shared__ float red[64 * 17];

    int t = threadIdx.x;
    int vt = blockIdx.x, g = blockIdx.y, b = blockIdx.z;

    const float4* wp = (const float4*)(W + (size_t)g * 4096);
    const float4* hp = (const float4*)(h + (((size_t)b * G_ + g) * V_ + (size_t)vt * 64) * 64);
    float4* sw4 = (float4*)sW;
    float4* sh4 = (float4*)sH;
#pragma unroll
    for (int q = t; q < 1024; q += 256) { sw4[q] = wp[q]; sh4[q] = hp[q]; }
    __syncthreads();

    int tx = t & 15, ty = t >> 4;
    int o0 = tx * 4, r0 = ty * 4;
    float acc[4][4] = {};
#pragma unroll 4
    for (int i = 0; i < 64; i++) {
        float4 bb = *(const float4*)(sW + i * 64 + o0);
#pragma unroll
        for (int r = 0; r < 4; r++) {
            float a = sH[(r0 + r) * 64 + i];
            acc[r][0] += a * bb.x; acc[r][1] += a * bb.y;
            acc[r][2] += a * bb.z; acc[r][3] += a * bb.w;
        }
    }

    float cs[4] = {0.f, 0.f, 0.f, 0.f};
#pragma unroll
    for (int r = 0; r < 4; r++) {
        float4 v;
        v.x = lrelu(acc[r][0]); v.y = lrelu(acc[r][1]);
        v.z = lrelu(acc[r][2]); v.w = lrelu(acc[r][3]);
        size_t row = (size_t)b * V_ + vt * 64 + r0 + r;
        *(float4*)(g_Wh + row * C_ + g * 64 + o0) = v;
        cs[0] += v.x; cs[1] += v.y; cs[2] += v.z; cs[3] += v.w;
    }
    __syncthreads();
#pragma unroll
    for (int j = 0; j < 4; j++) red[(o0 + j) * 17 + ty] = cs[j];
    __syncthreads();
    if (t < 64) {
        float s = 0.f;
#pragma unroll
        for (int k = 0; k < 16; k++) s += red[t * 17 + k];
        g_Spart[((size_t)b * 16 + vt) * C_ + g * 64 + t] = s;
    }
}

// ---------------- K1b: reduce partial sums -> S ----------------
__global__ void k_sreduce() {
    int b = blockIdx.x, c = threadIdx.x;   // 8 blocks x 512
    float s = 0.f;
#pragma unroll
    for (int vt = 0; vt < 16; vt++) s += g_Spart[((size_t)b * 16 + vt) * C_ + c];
    g_S[b * C_ + c] = s;
}

// ---------------- K3: assemble feature_in / feature_out planes ----------------
__global__ void __launch_bounds__(512) k_feat() {
    int i = blockIdx.x, b = blockIdx.y;
    int c = threadIdx.x;
    __shared__ short jlist[64];
    __shared__ int njs;
    __shared__ float sdeg;

    if (c == 0) sdeg = (float)(V_ - g_zcol[b * V_ + i]) * (1.0f / V_);
    if (c < 32) {
        unsigned mw = g_rowmask[((size_t)b * V_ + i) * 32 + c];
        int cnt = __popc(mw);
        int pre = cnt;
#pragma unroll
        for (int d = 1; d < 32; d <<= 1) {
            int v = __shfl_up_sync(0xffffffffu, pre, d);
            if (c >= d) pre += v;
        }
        int excl = pre - cnt;
        if (c == 31) njs = pre;
        while (mw) {
            int p = __ffs(mw) - 1;
            mw &= mw - 1;
            jlist[excl++] = (short)(c * 32 + p);
        }
    }
    __syncthreads();

    float S = g_S[b * C_ + c];
    float corr = 0.f;
    int n = njs;
    const float* whb = g_Wh + (size_t)b * V_ * C_ + c;
#pragma unroll 1
    for (int k = 0; k < n; k += 4) {
        float v0 = whb[(size_t)jlist[k] * C_];
        float v1 = (k + 1 < n) ? whb[(size_t)jlist[k + 1] * C_] : 0.f;
        float v2 = (k + 2 < n) ? whb[(size_t)jlist[k + 2] * C_] : 0.f;
        float v3 = (k + 3 < n) ? whb[(size_t)jlist[k + 3] * C_] : 0.f;
        corr += (v0 + v1) + (v2 + v3);
    }
    float fout = lrelu((S - corr) * (1.0f / V_));
    float fin  = lrelu(sdeg * whb[(size_t)i * C_]);

    int g = c >> 6, o = c & 63;
    size_t oidx = (((size_t)b * G_ + g) * V_ + i) * FOUT_ + o;
    g_featin[oidx]  = fin;
    g_featout[oidx] = fout;
}

// ---------------- K4: 5x5 conv, f32x2 lanes = adjacent output columns ---------
// grid (V/16, B, 2). block 512 = cg(8) x rg(8) x g(8). Thread: 1 g, 2 rows,
// 8 cols (4 ull col-pairs per row). Even-kw taps use natively aligned LDS
// register pairs (no MOV); odd-kw taps need 5 packs/row. Weights pre-broadcast
// as ull in smem. launch_bounds(512,2) caps regs at 64 -> 2 CTAs/SM.
#define TW_ 76                               // padded tile width (floats)
#define TILE_OFF 0
#define WT_OFF   (8 * 20 * TW_ * 4)          // 48640
#define SB_OFF   (WT_OFF + 1600 * 8)         // + 12800
#define CONV_SMEM (SB_OFF + 64)

__global__ void __launch_bounds__(512, 2) k_conv(const float* __restrict__ cw1,
                                                 const float* __restrict__ cb1,
                                                 const float* __restrict__ cw2,
                                                 const float* __restrict__ cb2,
                                                 float* __restrict__ out) {
    extern __shared__ char sm_[];
    float* tile = (float*)(sm_ + TILE_OFF);   // [8][20][76]
    ull*   wts  = (ull*)(sm_ + WT_OFF);       // [g][cin][25], both lanes = w
    float* sb   = (float*)(sm_ + SB_OFF);     // [8]

    int which = blockIdx.z;
    int b = blockIdx.y;
    int r0 = blockIdx.x * 16;
    int t = threadIdx.x;

    const float* feat = which ? g_featout : g_featin;
    const float* cw   = which ? cw2 : cw1;
    const float* cb   = which ? cb2 : cb1;

    for (int q = t; q < 1600; q += 512) {
        float w = cw[q];
        wts[q] = pack2(w, w);
    }
    if (t < 8) sb[t] = cb[t];

    // stage main tile cols 0..63 (8 cin x 20 rows x 16 float4)
#pragma unroll 1
    for (int q = t; q < 2560; q += 512) {
        int cin = q / 320;
        int rem = q - cin * 320;
        int row = rem >> 4;
        int o4  = rem & 15;
        int v = r0 - 2 + row;
        float4 val = make_float4(0.f, 0.f, 0.f, 0.f);
        if (v >= 0 && v < V_)
            val = *(const float4*)(feat + (((size_t)b * G_ + cin) * V_ + v) * FOUT_ + o4 * 4);
        *(float4*)(tile + (cin * 20 + row) * TW_ + o4 * 4) = val;
    }
    // zero pad cols 64..75 (8 cin x 20 rows x 3 float4)
    for (int q = t; q < 480; q += 512) {
        int cin = q / 60;
        int rem = q - cin * 60;
        int row = rem / 3;
        int o4  = rem % 3;
        *(float4*)(tile + (cin * 20 + row) * TW_ + 64 + o4 * 4) =
            make_float4(0.f, 0.f, 0.f, 0.f);
    }
    __syncthreads();

    int cg = t & 7, rg = (t >> 3) & 7, g = t >> 6;
    int w0 = cg * 8;
    int lr = rg * 2;

    float bv = sb[g];
    ull bias = pack2(bv, bv);
    ull acc[2][4];
#pragma unroll
    for (int r = 0; r < 2; r++)
#pragma unroll
        for (int cc = 0; cc < 4; cc++) acc[r][cc] = bias;

#pragma unroll 1
    for (int cin = 0; cin < 8; cin++) {
        const ull* wp = wts + (g * 8 + cin) * 25;
        const float* pa = tile + (cin * 20 + lr) * TW_ + w0;
#pragma unroll
        for (int ri = 0; ri < 6; ri++) {
            float4 A = *(const float4*)(pa + ri * TW_);
            float4 Bq = *(const float4*)(pa + ri * TW_ + 4);
            float4 Cq = *(const float4*)(pa + ri * TW_ + 8);
            ull xe[6], xo[5];
            xe[0] = pack2(A.x, A.y);  xe[1] = pack2(A.z, A.w);
            xe[2] = pack2(Bq.x, Bq.y); xe[3] = pack2(Bq.z, Bq.w);
            xe[4] = pack2(Cq.x, Cq.y); xe[5] = pack2(Cq.z, Cq.w);
            xo[0] = pack2(A.y, A.z);  xo[1] = pack2(A.w, Bq.x);
            xo[2] = pack2(Bq.y, Bq.z); xo[3] = pack2(Bq.w, Cq.x);
            xo[4] = pack2(Cq.y, Cq.z);
#pragma unroll
            for (int r = 0; r < 2; r++) {
                int kh = ri - r;
                if (kh < 0 || kh > 4) continue;
                const ull* wk = wp + kh * 5;
                // kw = 0, 2, 4 (even: aligned pairs)
#pragma unroll
                for (int ke = 0; ke < 3; ke++) {
                    ull wt = wk[2 * ke];
#pragma unroll
                    for (int cc = 0; cc < 4; cc++)
                        acc[r][cc] = fma2(xe[ke + cc], wt, acc[r][cc]);
                }
                // kw = 1, 3 (odd: shifted pairs)
#pragma unroll
                for (int ko = 0; ko < 2; ko++) {
                    ull wt = wk[2 * ko + 1];
#pragma unroll
                    for (int cc = 0; cc < 4; cc++)
                        acc[r][cc] = fma2(xo[ko + cc], wt, acc[r][cc]);
                }
            }
        }
    }

#pragma unroll
    for (int r = 0; r < 2; r++) {
        float2 u0 = unpack2(acc[r][0]);
        float2 u1 = unpack2(acc[r][1]);
        float2 u2 = unpack2(acc[r][2]);
        float2 u3 = unpack2(acc[r][3]);
        int v = r0 + lr + r;
        size_t base = (((size_t)b * G_ + g) * V_ + v) * OUTC_ + which * OUTW_ + w0;
        *(float4*)(out + base) = make_float4(u0.x, u0.y, u1.x, u1.y);
        if (cg < 7)
            *(float4*)(out + base + 4) = make_float4(u2.x, u2.y, u3.x, u3.y);
    }
}

// ---------------- launch ----------------
extern "C" void kernel_launch(void* const* d_in, const int* in_sizes, int n_in,
                              void* d_out, int out_size) {
    const float* h       = (const float*)d_in[0];
    const int*   adj     = (const int*)d_in[1];
    const float* W       = (const float*)d_in[2];
    const float* conv1_w = (const float*)d_in[3];
    const float* conv1_b = (const float*)d_in[4];
    const float* conv2_w = (const float*)d_in[5];
    const float* conv2_b = (const float*)d_in[6];
    float* out = (float*)d_out;

    cudaFuncSetAttribute(k_conv, cudaFuncAttributeMaxDynamicSharedMemorySize, CONV_SMEM);

    // adj FIRST: its 268MB stream would evict g_Wh from L2 if run after k_wh.
    k_zero<<<8, 1024>>>();
    k_adj<<<dim3(V_, B_), 256>>>(adj);
    k_wh<<<dim3(16, G_, B_), 256>>>(h, W);
    k_sreduce<<<B_, 512>>>();
    k_feat<<<dim3(V_, B_), 512>>>();
    k_conv<<<dim3(V_ / 16, B_, 2), 512, CONV_SMEM>>>(conv1_w, conv1_b, conv2_w, conv2_b, out);
}

// round 6
// speedup vs baseline: 1.4331x; 1.2083x over previous
#include <cuda_runtime.h>

#define ALPHA 0.2f
#define B_   8
#define G_   8
#define V_   1024
#define FIN_ 64
#define FOUT_ 64
#define C_   512            // G_*FOUT_
#define OUTW_ 60            // FOUT_-4
#define OUTC_ 120           // 2*OUTW_

typedef unsigned long long ull;

// ---------------- scratch (device globals; no allocation) ----------------
__device__ __align__(16) float    g_Wh[B_*V_*C_];        // [b][v][c] leaky(Wh)
__device__ float                  g_Spart[B_*16*C_];     // partial col sums per v-tile
__device__ float                  g_S[B_*C_];            // col sums of leaky(Wh)
__device__ unsigned               g_rowmask[B_*V_*32];   // bit j set <=> a[b,i,j]==0
__device__ int                    g_zcol[B_*V_];         // zero count per column v
__device__ __align__(16) float    g_featin[B_*G_*V_*FOUT_];
__device__ __align__(16) float    g_featout[B_*G_*V_*FOUT_];

__device__ __forceinline__ float lrelu(float x) { return x >= 0.f ? x : ALPHA * x; }

// ---- packed fp32x2 helpers ----
__device__ __forceinline__ ull pack2(float x, float y) {
    ull r;
    asm("mov.b64 %0, {%1, %2};" : "=l"(r) : "f"(x), "f"(y));
    return r;
}
__device__ __forceinline__ ull bcast2(float x) {
    ull r;
    asm("mov.b64 %0, {%1, %1};" : "=l"(r) : "f"(x));
    return r;
}
__device__ __forceinline__ ull fma2(ull a, ull b, ull c) {
    ull d;
    asm("fma.rn.f32x2 %0, %1, %2, %3;" : "=l"(d) : "l"(a), "l"(b), "l"(c));
    return d;
}
__device__ __forceinline__ float2 unpack2(ull v) {
    float2 r;
    asm("mov.b64 {%0, %1}, %2;" : "=f"(r.x), "=f"(r.y) : "l"(v));
    return r;
}

// ---------------- K0: zero the column-zero counters ----------------
__global__ void k_zero() {
    int t = blockIdx.x * blockDim.x + threadIdx.x;
    if (t < B_ * V_) g_zcol[t] = 0;
}

// ---------------- K2: adj scan -> zero-edge bitmask + column zero counts ------
__global__ void __launch_bounds__(256) k_adj(const int* __restrict__ adj) {
    int i = blockIdx.x, b = blockIdx.y;
    __shared__ unsigned mask[32];
    int t = threadIdx.x;
    if (t < 32) mask[t] = 0u;
    __syncthreads();

    const int4* p = (const int4*)(adj + (size_t)b * G_ * V_ * V_ + (size_t)i * V_);
    int4 acc = p[t];
#pragma unroll
    for (int g = 1; g < G_; g++) {
        int4 v = p[(size_t)g * (V_ * (V_ / 4)) + t];
        acc.x |= v.x; acc.y |= v.y; acc.z |= v.z; acc.w |= v.w;
    }
    unsigned nib = (unsigned)(acc.x == 0) | ((unsigned)(acc.y == 0) << 1) |
                   ((unsigned)(acc.z == 0) << 2) | ((unsigned)(acc.w == 0) << 3);
    if (nib) {
        atomicOr(&mask[t >> 3], nib << ((t & 7) * 4));
        int jb = b * V_ + 4 * t;
        if (acc.x == 0) atomicAdd(&g_zcol[jb + 0], 1);
        if (acc.y == 0) atomicAdd(&g_zcol[jb + 1], 1);
        if (acc.z == 0) atomicAdd(&g_zcol[jb + 2], 1);
        if (acc.w == 0) atomicAdd(&g_zcol[jb + 3], 1);
    }
    __syncthreads();
    if (t < 32) g_rowmask[((size_t)b * V_ + i) * 32 + t] = mask[t];
}

// ---------------- K1: Wh = leaky(h @ W) per (b,g); also partial column sums ----
__global__ void __launch_bounds__(256) k_wh(const float* __restrict__ h,
                                            const float* __restrict__ W) {
    __shared__ __align__(16) float sW[64 * 64];   // [i][o]
    __shared__ __align__(16) float sH[64 * 64];   // [v][i]
    __shared__ float red[64 * 17];

    int t = threadIdx.x;
    int vt = blockIdx.x, g = blockIdx.y, b = blockIdx.z;

    const float4* wp = (const float4*)(W + (size_t)g * 4096);
    const float4* hp = (const float4*)(h + (((size_t)b * G_ + g) * V_ + (size_t)vt * 64) * 64);
    float4* sw4 = (float4*)sW;
    float4* sh4 = (float4*)sH;
#pragma unroll
    for (int q = t; q < 1024; q += 256) { sw4[q] = wp[q]; sh4[q] = hp[q]; }
    __syncthreads();

    int tx = t & 15, ty = t >> 4;
    int o0 = tx * 4, r0 = ty * 4;
    float acc[4][4] = {};
#pragma unroll 4
    for (int i = 0; i < 64; i++) {
        float4 bb = *(const float4*)(sW + i * 64 + o0);
#pragma unroll
        for (int r = 0; r < 4; r++) {
            float a = sH[(r0 + r) * 64 + i];
            acc[r][0] += a * bb.x; acc[r][1] += a * bb.y;
            acc[r][2] += a * bb.z; acc[r][3] += a * bb.w;
        }
    }

    float cs[4] = {0.f, 0.f, 0.f, 0.f};
#pragma unroll
    for (int r = 0; r < 4; r++) {
        float4 v;
        v.x = lrelu(acc[r][0]); v.y = lrelu(acc[r][1]);
        v.z = lrelu(acc[r][2]); v.w = lrelu(acc[r][3]);
        size_t row = (size_t)b * V_ + vt * 64 + r0 + r;
        *(float4*)(g_Wh + row * C_ + g * 64 + o0) = v;
        cs[0] += v.x; cs[1] += v.y; cs[2] += v.z; cs[3] += v.w;
    }
    __syncthreads();
#pragma unroll
    for (int j = 0; j < 4; j++) red[(o0 + j) * 17 + ty] = cs[j];
    __syncthreads();
    if (t < 64) {
        float s = 0.f;
#pragma unroll
        for (int k = 0; k < 16; k++) s += red[t * 17 + k];
        g_Spart[((size_t)b * 16 + vt) * C_ + g * 64 + t] = s;
    }
}

// ---------------- K1b: reduce partial sums -> S (64 blocks: latency) ----------
__global__ void k_sreduce() {
    int b = blockIdx.x >> 3;
    int c = (blockIdx.x & 7) * 64 + threadIdx.x;
    float s = 0.f;
#pragma unroll
    for (int vt = 0; vt < 16; vt++) s += g_Spart[((size_t)b * 16 + vt) * C_ + c];
    g_S[b * C_ + c] = s;
}

// ---------------- K3: assemble feature_in / feature_out planes ----------------
__global__ void __launch_bounds__(512) k_feat() {
    int i = blockIdx.x, b = blockIdx.y;
    int c = threadIdx.x;
    __shared__ short jlist[64];
    __shared__ int njs;
    __shared__ float sdeg;

    if (c == 0) sdeg = (float)(V_ - g_zcol[b * V_ + i]) * (1.0f / V_);
    if (c < 32) {
        unsigned mw = g_rowmask[((size_t)b * V_ + i) * 32 + c];
        int cnt = __popc(mw);
        int pre = cnt;
#pragma unroll
        for (int d = 1; d < 32; d <<= 1) {
            int v = __shfl_up_sync(0xffffffffu, pre, d);
            if (c >= d) pre += v;
        }
        int excl = pre - cnt;
        if (c == 31) njs = pre;
        while (mw) {
            int p = __ffs(mw) - 1;
            mw &= mw - 1;
            jlist[excl++] = (short)(c * 32 + p);
        }
    }
    __syncthreads();

    float S = g_S[b * C_ + c];
    float corr = 0.f;
    int n = njs;
    const float* whb = g_Wh + (size_t)b * V_ * C_ + c;
#pragma unroll 1
    for (int k = 0; k < n; k += 4) {
        float v0 = whb[(size_t)jlist[k] * C_];
        float v1 = (k + 1 < n) ? whb[(size_t)jlist[k + 1] * C_] : 0.f;
        float v2 = (k + 2 < n) ? whb[(size_t)jlist[k + 2] * C_] : 0.f;
        float v3 = (k + 3 < n) ? whb[(size_t)jlist[k + 3] * C_] : 0.f;
        corr += (v0 + v1) + (v2 + v3);
    }
    float fout = lrelu((S - corr) * (1.0f / V_));
    float fin  = lrelu(sdeg * whb[(size_t)i * C_]);

    int g = c >> 6, o = c & 63;
    size_t oidx = (((size_t)b * G_ + g) * V_ + i) * FOUT_ + o;
    g_featin[oidx]  = fin;
    g_featout[oidx] = fout;
}

// ---------------- K4: 5x5 conv (R2-proven), f32x2 output-channel pairs --------
__global__ void __launch_bounds__(512) k_conv(const float* __restrict__ cw1,
                                              const float* __restrict__ cb1,
                                              const float* __restrict__ cw2,
                                              const float* __restrict__ cb2,
                                              float* __restrict__ out) {
    int which = blockIdx.z;
    int b = blockIdx.y;
    int r0 = blockIdx.x * 16;

    __shared__ __align__(16) float sin_[8][20][64];    // [cin][row][col], 40 KB
    __shared__ __align__(8) float2 swt2[4 * 8 * 25];   // [gg][cin][tap] -> (wt_g0, wt_g1)
    __shared__ float2 sb2[4];

    const float* feat = which ? g_featout : g_featin;
    const float* cw = which ? cw2 : cw1;
    const float* cb = which ? cb2 : cb1;

    int t = threadIdx.x;
    for (int q = t; q < 800; q += 512) {
        int gg = q / 200;
        int rem = q - gg * 200;      // cin*25 + tap
        swt2[q] = make_float2(cw[(2 * gg) * 200 + rem], cw[(2 * gg + 1) * 200 + rem]);
    }
    if (t < 4) sb2[t] = make_float2(cb[2 * t], cb[2 * t + 1]);

#pragma unroll
    for (int q = t; q < 2560; q += 512) {
        int cin = q / 320;
        int rem = q - cin * 320;
        int row = rem >> 4;
        int o4  = rem & 15;
        int v = r0 - 2 + row;
        float4 val = make_float4(0.f, 0.f, 0.f, 0.f);
        if (v >= 0 && v < V_)
            val = *(const float4*)(feat + (((size_t)b * G_ + cin) * V_ + v) * FOUT_ + o4 * 4);
        *(float4*)(&sin_[cin][row][o4 * 4]) = val;
    }
    __syncthreads();

    int cg = t & 15, rg = (t >> 4) & 7, gg = t >> 7;
    if (cg < 15) {
        int w0 = cg * 4;
        int lr = rg * 2;

        ull bias = pack2(sb2[gg].x, sb2[gg].y);
        ull acc[2][4];
#pragma unroll
        for (int r = 0; r < 2; r++)
#pragma unroll
            for (int c = 0; c < 4; c++) acc[r][c] = bias;

        const float2* wp = &swt2[gg * 200];

#pragma unroll 1
        for (int cin = 0; cin < 8; cin++) {
#pragma unroll
            for (int kh = 0; kh < 5; kh++) {
                ull in2[2][8];
#pragma unroll
                for (int rr = 0; rr < 2; rr++) {
                    float4 a4 = *(const float4*)(&sin_[cin][lr + kh + rr][w0]);
                    float4 b4 = *(const float4*)(&sin_[cin][lr + kh + rr][w0 + 4]);
                    in2[rr][0] = bcast2(a4.x); in2[rr][1] = bcast2(a4.y);
                    in2[rr][2] = bcast2(a4.z); in2[rr][3] = bcast2(a4.w);
                    in2[rr][4] = bcast2(b4.x); in2[rr][5] = bcast2(b4.y);
                    in2[rr][6] = bcast2(b4.z); in2[rr][7] = bcast2(b4.w);
                }
#pragma unroll
                for (int kw = 0; kw < 5; kw++) {
                    float2 w2 = wp[cin * 25 + kh * 5 + kw];
                    ull wt = pack2(w2.x, w2.y);
#pragma unroll
                    for (int r = 0; r < 2; r++) {
#pragma unroll
                        for (int c = 0; c < 4; c++)
                            acc[r][c] = fma2(in2[r][kw + c], wt, acc[r][c]);
                    }
                }
            }
        }

#pragma unroll
        for (int r = 0; r < 2; r++) {
            float2 u0 = unpack2(acc[r][0]);
            float2 u1 = unpack2(acc[r][1]);
            float2 u2 = unpack2(acc[r][2]);
            float2 u3 = unpack2(acc[r][3]);
            int v = r0 + lr + r;
            size_t base0 = (((size_t)b * G_ + (2 * gg)) * V_ + v) * OUTC_ + which * OUTW_ + w0;
            size_t base1 = (((size_t)b * G_ + (2 * gg + 1)) * V_ + v) * OUTC_ + which * OUTW_ + w0;
            *(float4*)(out + base0) = make_float4(u0.x, u1.x, u2.x, u3.x);
            *(float4*)(out + base1) = make_float4(u0.y, u1.y, u2.y, u3.y);
        }
    }
}

// ---------------- launch: fork adj (DRAM) ∥ wh+sreduce (FMA) ----------------
extern "C" void kernel_launch(void* const* d_in, const int* in_sizes, int n_in,
                              void* d_out, int out_size) {
    const float* h       = (const float*)d_in[0];
    const int*   adj     = (const int*)d_in[1];
    const float* W       = (const float*)d_in[2];
    const float* conv1_w = (const float*)d_in[3];
    const float* conv1_b = (const float*)d_in[4];
    const float* conv2_w = (const float*)d_in[5];
    const float* conv2_b = (const float*)d_in[6];
    float* out = (float*)d_out;

    // created once on the (uncaptured) correctness call; reused under capture
    static cudaStream_t s1 = nullptr;
    static cudaEvent_t ev0 = nullptr, ev1 = nullptr;
    if (s1 == nullptr) {
        cudaStreamCreateWithFlags(&s1, cudaStreamNonBlocking);
        cudaEventCreateWithFlags(&ev0, cudaEventDisableTiming);
        cudaEventCreateWithFlags(&ev1, cudaEventDisableTiming);
    }

    k_zero<<<8, 1024>>>();                                  // legacy stream
    cudaEventRecord(ev0, 0);
    cudaStreamWaitEvent(s1, ev0, 0);

    k_adj<<<dim3(V_, B_), 256>>>(adj);                      // legacy: DRAM-bound
    k_wh<<<dim3(16, G_, B_), 256, 0, s1>>>(h, W);           // s1: FMA-bound
    k_sreduce<<<64, 64, 0, s1>>>();                         // s1

    cudaEventRecord(ev1, s1);
    cudaStreamWaitEvent(0, ev1, 0);                         // join

    k_feat<<<dim3(V_, B_), 512>>>();
    k_conv<<<dim3(V_ / 16, B_, 2), 512>>>(conv1_w, conv1_b, conv2_w, conv2_b, out);
}